// round 5
// baseline (speedup 1.0000x reference)
#include <cuda_runtime.h>
#include <cuda_bf16.h>
#include <cstdint>

#define NPARAMS      1280
#define CLUSTER      8
#define SHARD        32768            // 262144 / 8
#define SHARD_SHIFT  15
#define EDGE_THREADS 1024
#define EDGE_CLUSTERS 16              // guaranteed single wave (8 clusters per 76-SM die)
#define EDGE_BLOCKS  (EDGE_CLUSTERS * CLUSTER)
#define SMEM_BYTES   ((NPARAMS + SHARD) * 4)

// out[i] = Param_b[b_params[i]]   (also the zero-init for the scatter)
__global__ void bias_init_kernel(const float* __restrict__ Pb,
                                 const int*   __restrict__ bidx,
                                 float*       __restrict__ out,
                                 int n) {
    int i = blockIdx.x * blockDim.x + threadIdx.x;
    if (i < n) {
        out[i] = __ldg(&Pb[__ldg(&bidx[i])]);
    }
}

// ---------------------------------------------------------------------------
// Cluster version: all of x lives in distributed shared memory across the
// 8-CTA cluster. Gathers use mapa + ld.shared::cluster instead of divergent
// global LDG (which was the dominant L1tex wavefront cost).
// Atomics stay as global REDG (L2-side atomic machine is wider than smem ports).
// ---------------------------------------------------------------------------
__global__ void __cluster_dims__(CLUSTER, 1, 1) __launch_bounds__(EDGE_THREADS, 1)
edge_scatter_cluster_kernel(const float* __restrict__ x,
                            const float* __restrict__ Pw,
                            const int*   __restrict__ rows,
                            const int*   __restrict__ cols,
                            const int*   __restrict__ params,
                            float*       __restrict__ out,
                            int nvec,   // E / 4
                            int tail,   // E % 4
                            int E) {
    extern __shared__ float smem[];
    float* sPw = smem;                 // [NPARAMS]
    float* sx  = smem + NPARAMS;       // [SHARD]

    uint32_t rank;
    asm("mov.u32 %0, %%cluster_ctarank;" : "=r"(rank));

    // Fill Param_W replica
    for (int i = threadIdx.x; i < NPARAMS; i += EDGE_THREADS)
        sPw[i] = Pw[i];

    // Fill this CTA's x shard (coalesced float4)
    {
        const float4* src = (const float4*)(x + rank * SHARD);
        float4*       dst = (float4*)sx;
        for (int i = threadIdx.x; i < SHARD / 4; i += EDGE_THREADS)
            dst[i] = src[i];
    }

    // Cluster barrier: all shards visible before any cross-CTA gather
    asm volatile("barrier.cluster.arrive.aligned;" ::: "memory");
    asm volatile("barrier.cluster.wait.aligned;"   ::: "memory");

    uint32_t sx_base;
    asm("{ .reg .u64 t; cvta.to.shared.u64 t, %1; cvt.u32.u64 %0, t; }"
        : "=r"(sx_base) : "l"(sx));

    const int4* __restrict__ rows4   = (const int4*)rows;
    const int4* __restrict__ cols4   = (const int4*)cols;
    const int4* __restrict__ params4 = (const int4*)params;

    int gtid   = blockIdx.x * blockDim.x + threadIdx.x;
    int stride = gridDim.x * blockDim.x;

    for (int v = gtid; v < nvec; v += 2 * stride) {
        int  v2 = v + stride;
        bool h2 = (v2 < nvec);

        int4 c0 = cols4[v];
        int4 p0 = params4[v];
        int4 r0 = rows4[v];
        int4 c1 = c0, p1 = p0, r1 = r0;
        if (h2) { c1 = cols4[v2]; p1 = params4[v2]; r1 = rows4[v2]; }

        int cidx[8] = {c0.x, c0.y, c0.z, c0.w, c1.x, c1.y, c1.z, c1.w};

        // Issue all 8 remote gathers up front (MLP covers the ~215cyc DSMEM latency)
        float g[8];
#pragma unroll
        for (int k = 0; k < 8; k++) {
            uint32_t col    = (uint32_t)cidx[k];
            uint32_t local  = sx_base + ((col & (SHARD - 1)) << 2);
            uint32_t remote;
            asm("mapa.shared::cluster.u32 %0, %1, %2;"
                : "=r"(remote) : "r"(local), "r"(col >> SHARD_SHIFT));
            asm("ld.shared::cluster.f32 %0, [%1];"
                : "=f"(g[k]) : "r"(remote));
        }

        atomicAdd(&out[r0.x], sPw[p0.x] * g[0]);
        atomicAdd(&out[r0.y], sPw[p0.y] * g[1]);
        atomicAdd(&out[r0.z], sPw[p0.z] * g[2]);
        atomicAdd(&out[r0.w], sPw[p0.w] * g[3]);
        if (h2) {
            atomicAdd(&out[r1.x], sPw[p1.x] * g[4]);
            atomicAdd(&out[r1.y], sPw[p1.y] * g[5]);
            atomicAdd(&out[r1.z], sPw[p1.z] * g[6]);
            atomicAdd(&out[r1.w], sPw[p1.w] * g[7]);
        }
    }

    // Tail (E % 4 != 0) — defensive; E = 2^24 here
    if (gtid < tail) {
        int e = E - tail + gtid;
        uint32_t col   = (uint32_t)cols[e];
        uint32_t local = sx_base + ((col & (SHARD - 1)) << 2);
        uint32_t remote;
        float gv;
        asm("mapa.shared::cluster.u32 %0, %1, %2;"
            : "=r"(remote) : "r"(local), "r"(col >> SHARD_SHIFT));
        asm("ld.shared::cluster.f32 %0, [%1];" : "=f"(gv) : "r"(remote));
        atomicAdd(&out[rows[e]], sPw[params[e]] * gv);
    }

    // No CTA may exit while peers can still read its shard
    asm volatile("barrier.cluster.arrive.aligned;" ::: "memory");
    asm volatile("barrier.cluster.wait.aligned;"   ::: "memory");
}

// ---------------------------------------------------------------------------
// Fallback (proven R4 kernel) for any shape where the cluster layout doesn't fit
// ---------------------------------------------------------------------------
__global__ void edge_scatter_kernel(const float* __restrict__ x,
                                    const float* __restrict__ Pw,
                                    const int*   __restrict__ rows,
                                    const int*   __restrict__ cols,
                                    const int*   __restrict__ params,
                                    float*       __restrict__ out,
                                    int nvec, int tail, int E) {
    __shared__ float sPw[NPARAMS];
    for (int i = threadIdx.x; i < NPARAMS; i += blockDim.x)
        sPw[i] = Pw[i];
    __syncthreads();

    const int4* __restrict__ rows4   = (const int4*)rows;
    const int4* __restrict__ cols4   = (const int4*)cols;
    const int4* __restrict__ params4 = (const int4*)params;

    int gtid   = blockIdx.x * blockDim.x + threadIdx.x;
    int stride = gridDim.x * blockDim.x;

    for (int v = gtid; v < nvec; v += stride) {
        int4 r = rows4[v];
        int4 c = cols4[v];
        int4 p = params4[v];

        float v0 = sPw[p.x] * __ldg(&x[c.x]);
        float v1 = sPw[p.y] * __ldg(&x[c.y]);
        float v2 = sPw[p.z] * __ldg(&x[c.z]);
        float v3 = sPw[p.w] * __ldg(&x[c.w]);

        atomicAdd(&out[r.x], v0);
        atomicAdd(&out[r.y], v1);
        atomicAdd(&out[r.z], v2);
        atomicAdd(&out[r.w], v3);
    }

    if (gtid < tail) {
        int e = E - tail + gtid;
        float val = sPw[params[e]] * __ldg(&x[cols[e]]);
        atomicAdd(&out[rows[e]], val);
    }
}

extern "C" void kernel_launch(void* const* d_in, const int* in_sizes, int n_in,
                              void* d_out, int out_size) {
    // metadata order: x, Param_W, Param_b, w_rows, w_cols, w_params, b_params
    const float* x        = (const float*)d_in[0];
    const float* Param_W  = (const float*)d_in[1];
    const float* Param_b  = (const float*)d_in[2];
    const int*   w_rows   = (const int*)d_in[3];
    const int*   w_cols   = (const int*)d_in[4];
    const int*   w_params = (const int*)d_in[5];
    const int*   b_params = (const int*)d_in[6];
    float*       out      = (float*)d_out;

    const int N = out_size;     // 262144
    const int E = in_sizes[3];  // 16777216

    // 1) bias init (must complete before scatter — same stream ordering)
    {
        int threads = 256;
        int blocks  = (N + threads - 1) / threads;
        bias_init_kernel<<<blocks, threads>>>(Param_b, b_params, out, N);
    }

    int nvec = E / 4;
    int tail = E - nvec * 4;

    if (N == CLUSTER * SHARD && in_sizes[1] == NPARAMS) {
        // 2a) cluster DSMEM gather version
        cudaFuncSetAttribute(edge_scatter_cluster_kernel,
                             cudaFuncAttributeMaxDynamicSharedMemorySize,
                             SMEM_BYTES);
        edge_scatter_cluster_kernel<<<EDGE_BLOCKS, EDGE_THREADS, SMEM_BYTES>>>(
            x, Param_W, w_rows, w_cols, w_params, out, nvec, tail, E);
    } else {
        // 2b) fallback: global-gather version
        int threads = 256;
        int blocks  = 152 * 8;
        edge_scatter_kernel<<<blocks, threads>>>(x, Param_W, w_rows, w_cols,
                                                 w_params, out, nvec, tail, E);
    }
}

// round 7
// speedup vs baseline: 2.8207x; 2.8207x over previous
#include <cuda_runtime.h>
#include <cuda_bf16.h>

#define NPARAMS 1280

// out[i] = Param_b[b_params[i]]   (also the zero-init for the scatter)
__global__ void bias_init_kernel(const float* __restrict__ Pb,
                                 const int*   __restrict__ bidx,
                                 float*       __restrict__ out,
                                 int n) {
    int v = blockIdx.x * blockDim.x + threadIdx.x;   // vec4 index
    int nvec = n >> 2;
    if (v < nvec) {
        int4 b = ((const int4*)bidx)[v];
        float4 o;
        o.x = __ldg(&Pb[b.x]);
        o.y = __ldg(&Pb[b.y]);
        o.z = __ldg(&Pb[b.z]);
        o.w = __ldg(&Pb[b.w]);
        ((float4*)out)[v] = o;
    }
    // scalar tail (defensive; n = 262144 here)
    int tail = n & 3;
    if (v < tail) {
        int i = n - tail + v;
        out[i] = __ldg(&Pb[__ldg(&bidx[i])]);
    }
}

// For each edge e: out[rows[e]] += Param_W[params[e]] * x[cols[e]]
// 8 edges per thread per grid-stride iteration (two coalesced int4 streams).
// Index streams use streaming loads (__ldcs) so the 1MB x stays L1-resident.
__global__ void __launch_bounds__(256, 6)
edge_scatter_kernel(const float* __restrict__ x,
                    const float* __restrict__ Pw,
                    const int*   __restrict__ rows,
                    const int*   __restrict__ cols,
                    const int*   __restrict__ params,
                    float*       __restrict__ out,
                    int nvec,   // E / 4
                    int tail,   // E % 4
                    int E) {
    __shared__ float sPw[NPARAMS];
    for (int i = threadIdx.x; i < NPARAMS; i += blockDim.x)
        sPw[i] = Pw[i];
    __syncthreads();

    const int4* __restrict__ rows4   = (const int4*)rows;
    const int4* __restrict__ cols4   = (const int4*)cols;
    const int4* __restrict__ params4 = (const int4*)params;

    int gtid   = blockIdx.x * blockDim.x + threadIdx.x;
    int stride = gridDim.x * blockDim.x;

    for (int v = gtid; v < nvec; v += 2 * stride) {
        int  v2 = v + stride;
        bool h2 = (v2 < nvec);

        // Streaming index loads (evict-first): don't pollute L1 for x
        int4 c0 = __ldcs(&cols4[v]);
        int4 p0 = __ldcs(&params4[v]);
        int4 r0 = __ldcs(&rows4[v]);
        int4 c1 = c0, p1 = p0, r1 = r0;
        if (h2) {
            c1 = __ldcs(&cols4[v2]);
            p1 = __ldcs(&params4[v2]);
            r1 = __ldcs(&rows4[v2]);
        }

        // Issue all 8 gathers up front (MLP covers L2/DRAM latency)
        float g0 = __ldg(&x[c0.x]);
        float g1 = __ldg(&x[c0.y]);
        float g2 = __ldg(&x[c0.z]);
        float g3 = __ldg(&x[c0.w]);
        float g4 = __ldg(&x[c1.x]);
        float g5 = __ldg(&x[c1.y]);
        float g6 = __ldg(&x[c1.z]);
        float g7 = __ldg(&x[c1.w]);

        atomicAdd(&out[r0.x], sPw[p0.x] * g0);
        atomicAdd(&out[r0.y], sPw[p0.y] * g1);
        atomicAdd(&out[r0.z], sPw[p0.z] * g2);
        atomicAdd(&out[r0.w], sPw[p0.w] * g3);
        if (h2) {
            atomicAdd(&out[r1.x], sPw[p1.x] * g4);
            atomicAdd(&out[r1.y], sPw[p1.y] * g5);
            atomicAdd(&out[r1.z], sPw[p1.z] * g6);
            atomicAdd(&out[r1.w], sPw[p1.w] * g7);
        }
    }

    // Tail edges (E % 4 != 0) — defensive; E = 2^24 here.
    if (gtid < tail) {
        int e = E - tail + gtid;
        float val = sPw[params[e]] * __ldg(&x[cols[e]]);
        atomicAdd(&out[rows[e]], val);
    }
}

extern "C" void kernel_launch(void* const* d_in, const int* in_sizes, int n_in,
                              void* d_out, int out_size) {
    // metadata order: x, Param_W, Param_b, w_rows, w_cols, w_params, b_params
    const float* x        = (const float*)d_in[0];
    const float* Param_W  = (const float*)d_in[1];
    const float* Param_b  = (const float*)d_in[2];
    const int*   w_rows   = (const int*)d_in[3];
    const int*   w_cols   = (const int*)d_in[4];
    const int*   w_params = (const int*)d_in[5];
    const int*   b_params = (const int*)d_in[6];
    float*       out      = (float*)d_out;

    const int N = out_size;     // 262144
    const int E = in_sizes[3];  // 16777216

    // 1) bias init (ordered before scatter on the same stream)
    {
        int threads = 256;
        int nvec    = N >> 2;
        int blocks  = (nvec + threads - 1) / threads;
        if (blocks < 1) blocks = 1;
        bias_init_kernel<<<blocks, threads>>>(Param_b, b_params, out, N);
    }

    // 2) edge scatter: single clean wave at 6 CTAs/SM x 152 SMs
    {
        int nvec    = E / 4;
        int tail    = E - nvec * 4;
        int threads = 256;
        int blocks  = 152 * 6;
        edge_scatter_kernel<<<blocks, threads>>>(x, Param_W, w_rows, w_cols,
                                                 w_params, out, nvec, tail, E);
    }
}